// round 15
// baseline (speedup 1.0000x reference)
#include <cuda_runtime.h>
#include <cuda_bf16.h>
#include <cstring>

#define BB 128
#define TT 512
#define II 128
#define HH 256

__device__ float g_xp[(size_t)BB * TT * HH];   // [B][T][H] fp32 scratch (fits L2)

// Packed fp32x2 FMA (sm_103a).
__device__ __forceinline__ float2 ffma2(float2 a, float2 b, float2 c) {
    unsigned long long ua, ub, uc, ud;
    memcpy(&ua, &a, 8); memcpy(&ub, &b, 8); memcpy(&uc, &c, 8);
    asm("fma.rn.f32x2 %0, %1, %2, %3;" : "=l"(ud) : "l"(ua), "l"(ub), "l"(uc));
    float2 d; memcpy(&d, &ud, 8); return d;
}

// Safe fast tanh: e = exp(-2|x|) in (0,1] -> no overflow; validated rel_err 6e-8.
__device__ __forceinline__ float fast_tanh(float x) {
    float e = __expf(-2.0f * fabsf(x));
    float r = __fdividef(1.0f - e, 1.0f + e);
    return copysignf(r, x);
}

// Pack two fp32 -> one u32 of bf16 (round-to-nearest), lo in low half.
__device__ __forceinline__ unsigned f2_to_bf2(float a, float b) {
    unsigned short ua = __bfloat16_as_ushort(__float2bfloat16_rn(a));
    unsigned short ub = __bfloat16_as_ushort(__float2bfloat16_rn(b));
    return (unsigned)ua | ((unsigned)ub << 16);
}

// Decompress pair: lo = one shift; hi = u32 reinterpreted directly (low 16
// garbage bits perturb <=2^-9 relative — VALIDATED R13/R14: rel_err 1.78e-4).
__device__ __forceinline__ float2 bf2_lo_higarbage(unsigned u) {
    float2 r;
    r.x = __uint_as_float(u << 16);
    r.y = __uint_as_float(u);
    return r;
}

// ---------------------------------------------------------------------------
// Phase 1: xp[r,h] = x[r,:] . W_ih[h,:] + (b_ih[h] + b_hh[h])
// PARITY-PAIR LAYOUT: 128 CTAs x 512 threads. Unchanged (fp32 exact).
// ---------------------------------------------------------------------------
__global__ void __launch_bounds__(512, 1)
rnn_xproj(const float* __restrict__ x,
          const float* __restrict__ W_ih,
          const float* __restrict__ b_ih,
          const float* __restrict__ b_hh) {
    __shared__ float xs[2][8 * II];               // 2 x 4 KB (8 rows/tile)

    const int tid  = threadIdx.x;
    const int lane = tid & 31;
    const int w    = tid >> 5;
    const int j    = (w << 4) | (lane >> 1);      // feature 0..255
    const int p    = lane & 1;

    const float4* Wi4 = (const float4*)W_ih;      // row j = Wi4[j*32 .. +31]
    float4 wreg[16];
#pragma unroll
    for (int qq = 0; qq < 16; qq++) wreg[qq] = Wi4[j * 32 + 2 * qq + p];

    const float bias = b_ih[j] + b_hh[j];
    const size_t base_row = (size_t)blockIdx.x * 512;

    if (tid < 256)
        ((float4*)xs[0])[tid] = ((const float4*)(x + base_row * II))[tid];
    __syncthreads();

    for (int tile = 0; tile < 64; tile++) {
        const int cur = tile & 1;
        if (tile < 63 && tid < 256) {
            ((float4*)xs[cur ^ 1])[tid] =
                ((const float4*)(x + (base_row + (size_t)(tile + 1) * 8) * II))[tid];
        }

        const size_t r0 = base_row + (size_t)tile * 8;
#pragma unroll
        for (int r = 0; r < 8; r++) {
            const float4* xr = (const float4*)(xs[cur] + r * II);
            float2 a0 = make_float2(0.0f, 0.0f), a1 = a0, a2 = a0, a3 = a0;
#pragma unroll
            for (int qq = 0; qq < 16; qq++) {
                float4 xv = xr[2 * qq + p];
                if (qq & 1) {
                    a2 = ffma2(make_float2(xv.x, xv.y), make_float2(wreg[qq].x, wreg[qq].y), a2);
                    a3 = ffma2(make_float2(xv.z, xv.w), make_float2(wreg[qq].z, wreg[qq].w), a3);
                } else {
                    a0 = ffma2(make_float2(xv.x, xv.y), make_float2(wreg[qq].x, wreg[qq].y), a0);
                    a1 = ffma2(make_float2(xv.z, xv.w), make_float2(wreg[qq].z, wreg[qq].w), a1);
                }
            }
            float dot = ((a0.x + a0.y) + (a1.x + a1.y)) +
                        ((a2.x + a2.y) + (a3.x + a3.y));
            dot += __shfl_xor_sync(0xffffffffu, dot, 1);   // combine parities
            if (p == 0)
                g_xp[(r0 + r) * HH + j] = dot + bias;      // 16 consec floats/warp
        }
        __syncthreads();
    }
}

// ---------------------------------------------------------------------------
// Phase 2 + 3: recurrent scan — K-QUARTER x 2-FEATURE, ALL-REGISTER BF16 W.
// 128 CTAs x 512 threads (16 warps). Warp w, lane l: slot f = l>>2 (0..7),
// quarter kq = l&3. Thread computes features jA = w*16+f and jB = jA+8 over
// h/W float4 indices {4*qq + kq}, qq = 0..15.
//   - W: 2 x 64 values = 64 bf16-pair u32 REGISTERS. NO SMEM weight tail.
//   - h: 16 LDS.128/thread, EACH feeding both features; all 8 slots of a
//     warp read the same 64B run -> 1 wf -> h-wf 512 -> 256 per step.
//   - crossbar/step ~850 (R12) -> ~280 wf. Decompress on ALU pipe.
//   - reduction: shfl.xor 1 & 2 over kq lanes; kq==0 publishes both
//     features. ONE __syncthreads per step.
//   - only 16 h-loads live per step (vs 32 in spilled R13) -> ~100 regs.
// ---------------------------------------------------------------------------
__global__ void __launch_bounds__(512, 1)
rnn_scan(const float* __restrict__ W_hh,
         const float* __restrict__ W_fc,
         const float* __restrict__ b_fc,
         float* __restrict__ out) {
    __shared__ __align__(16) float hA[HH];
    __shared__ __align__(16) float hB[HH];
    __shared__ float red[8];

    const int tid  = threadIdx.x;
    const int lane = tid & 31;
    const int w    = tid >> 5;
    const int f    = lane >> 2;                 // 0..7
    const int kq   = lane & 3;                  // 0..3
    const int jA   = (w << 4) | f;              // 0..247
    const int jB   = jA + 8;                    // 8..255
    const int b    = blockIdx.x;

    const float4* W4 = (const float4*)W_hh;     // row j = W4[j*64 .. +63]

    // Pack both features' k-quarter slices: 2 x 32 u32 registers.
    unsigned wA[32], wB[32];
#pragma unroll
    for (int qq = 0; qq < 16; qq++) {
        float4 a = W4[jA * 64 + 4 * qq + kq];
        float4 c = W4[jB * 64 + 4 * qq + kq];
        wA[2 * qq]     = f2_to_bf2(a.x, a.y);
        wA[2 * qq + 1] = f2_to_bf2(a.z, a.w);
        wB[2 * qq]     = f2_to_bf2(c.x, c.y);
        wB[2 * qq + 1] = f2_to_bf2(c.z, c.w);
    }

    if (tid < HH) { hA[tid] = 0.0f; hB[tid] = 0.0f; }
    __syncthreads();

    const float* xpA = g_xp + (size_t)b * TT * HH + jA;
    const float* xpB = g_xp + (size_t)b * TT * HH + jB;

    float* hcur = hA;
    float* hnxt = hB;

    float xvA = 0.0f, xvB = 0.0f;
    if (kq == 0) { xvA = xpA[0]; xvB = xpB[0]; }   // pipeline head

    for (int t = 0; t < TT; t++) {
        const float4* hs4 = (const float4*)hcur;
        float2 aA0 = make_float2(0.0f, 0.0f), aA1 = aA0;
        float2 aB0 = aA0, aB1 = aA0;

#pragma unroll
        for (int qq = 0; qq < 16; qq++) {
            float4 h4 = hs4[4 * qq + kq];       // 64B warp run: 1 wavefront
            float2 h01 = make_float2(h4.x, h4.y);
            float2 h23 = make_float2(h4.z, h4.w);
            aA0 = ffma2(h01, bf2_lo_higarbage(wA[2 * qq]),     aA0);
            aA1 = ffma2(h23, bf2_lo_higarbage(wA[2 * qq + 1]), aA1);
            aB0 = ffma2(h01, bf2_lo_higarbage(wB[2 * qq]),     aB0);
            aB1 = ffma2(h23, bf2_lo_higarbage(wB[2 * qq + 1]), aB1);
        }

        // prefetch next step's xp while the exchange/tanh drains
        float xnA = 0.0f, xnB = 0.0f;
        if (kq == 0 && t + 1 < TT) {
            xnA = xpA[(size_t)(t + 1) * HH];
            xnB = xpB[(size_t)(t + 1) * HH];
        }

        float dA = (aA0.x + aA0.y) + (aA1.x + aA1.y);
        float dB = (aB0.x + aB0.y) + (aB1.x + aB1.y);

        // reduce over the 4 kq lanes
        dA += __shfl_xor_sync(0xffffffffu, dA, 1);
        dB += __shfl_xor_sync(0xffffffffu, dB, 1);
        dA += __shfl_xor_sync(0xffffffffu, dA, 2);
        dB += __shfl_xor_sync(0xffffffffu, dB, 2);

        if (kq == 0) {
            hnxt[jA] = fast_tanh(xvA + dA);     // 16 consec floats per warp
            hnxt[jB] = fast_tanh(xvB + dB);
        }
        __syncthreads();                        // single barrier per step

        xvA = xnA; xvB = xnB;
        float* tmp = hcur; hcur = hnxt; hnxt = tmp;
    }

    // Phase 3: out[b] = sigmoid(h . W_fc + b_fc)
    if (tid < HH) {
        float v = hcur[tid] * W_fc[tid];
#pragma unroll
        for (int o = 16; o > 0; o >>= 1) v += __shfl_down_sync(0xffffffffu, v, o);
        if ((tid & 31) == 0) red[tid >> 5] = v;
    }
    __syncthreads();
    if (tid == 0) {
        float s = b_fc[0];
#pragma unroll
        for (int w2 = 0; w2 < 8; w2++) s += red[w2];
        out[b] = 1.0f / (1.0f + expf(-s));
    }
}

// ---------------------------------------------------------------------------

extern "C" void kernel_launch(void* const* d_in, const int* in_sizes, int n_in,
                              void* d_out, int out_size) {
    const float* x    = (const float*)d_in[0];
    const float* W_ih = (const float*)d_in[1];
    const float* W_hh = (const float*)d_in[2];
    const float* b_ih = (const float*)d_in[3];
    const float* b_hh = (const float*)d_in[4];
    const float* W_fc = (const float*)d_in[5];
    const float* b_fc = (const float*)d_in[6];
    float* out = (float*)d_out;

    rnn_xproj<<<128, 512>>>(x, W_ih, b_ih, b_hh);
    rnn_scan<<<BB, 512>>>(W_hh, W_fc, b_fc, out);
}

// round 16
// speedup vs baseline: 1.9802x; 1.9802x over previous
#include <cuda_runtime.h>
#include <cuda_bf16.h>
#include <cstring>

#define BB 128
#define TT 512
#define II 128
#define HH 256

__device__ float g_xp[(size_t)BB * TT * HH];   // [B][T][H] fp32 scratch (fits L2)

// Packed fp32x2 FMA (sm_103a).
__device__ __forceinline__ float2 ffma2(float2 a, float2 b, float2 c) {
    unsigned long long ua, ub, uc, ud;
    memcpy(&ua, &a, 8); memcpy(&ub, &b, 8); memcpy(&uc, &c, 8);
    asm("fma.rn.f32x2 %0, %1, %2, %3;" : "=l"(ud) : "l"(ua), "l"(ub), "l"(uc));
    float2 d; memcpy(&d, &ud, 8); return d;
}

// Safe fast tanh: e = exp(-2|x|) in (0,1] -> no overflow.
__device__ __forceinline__ float fast_tanh(float x) {
    float e = __expf(-2.0f * fabsf(x));
    float r = __fdividef(1.0f - e, 1.0f + e);
    return copysignf(r, x);
}

// Pack two fp32 -> one u32 of bf16 (round-to-nearest), lo in low half.
__device__ __forceinline__ unsigned f2_to_bf2(float a, float b) {
    unsigned short ua = __bfloat16_as_ushort(__float2bfloat16_rn(a));
    unsigned short ub = __bfloat16_as_ushort(__float2bfloat16_rn(b));
    return (unsigned)ua | ((unsigned)ub << 16);
}

// Decompress pair: lo = one shift; hi = u32 reinterpreted directly (low 16
// garbage bits perturb <=2^-9 relative — validated R13/R14: rel_err 1.78e-4).
__device__ __forceinline__ float2 bf2_lo_higarbage(unsigned u) {
    float2 r;
    r.x = __uint_as_float(u << 16);
    r.y = __uint_as_float(u);
    return r;
}

// ---------------------------------------------------------------------------
// Phase 1: xp[r,h] = x[r,:] . W_ih[h,:] + (b_ih[h] + b_hh[h])
// K-QUARTER x 2-FEATURE layout, bf16 W_ih registers (32 cold u32/thread —
// half the proven 64-u32 spill threshold). 128 CTAs x 512 threads.
// Warp w, lane l: slot f = l>>2, quarter kq = l&3; features jA = w*16+f,
// jB = jA+8; x/W float4 indices {4*qq + kq}, qq = 0..7.
//   - each x float4 (1 wf: 64B warp run) feeds BOTH features ->
//     x-crossbar per row halves (256 -> 128 wf) -> fma is the sole floor.
//   - 16-row tiles double-buffered; ALL 512 threads load (1 f4 each).
//   - reduction: shfl.xor 1 & 2; kq==0 stores both features.
// ---------------------------------------------------------------------------
__global__ void __launch_bounds__(512, 1)
rnn_xproj(const float* __restrict__ x,
          const float* __restrict__ W_ih,
          const float* __restrict__ b_ih,
          const float* __restrict__ b_hh) {
    __shared__ float xs[2][16 * II];              // 2 x 8 KB (16 rows/tile)

    const int tid  = threadIdx.x;
    const int lane = tid & 31;
    const int w    = tid >> 5;
    const int f    = lane >> 2;                   // 0..7
    const int kq   = lane & 3;                    // 0..3
    const int jA   = (w << 4) | f;                // 0..247
    const int jB   = jA + 8;                      // 8..255

    const float4* Wi4 = (const float4*)W_ih;      // row j = Wi4[j*32 .. +31]
    unsigned wA[16], wB[16];
#pragma unroll
    for (int qq = 0; qq < 8; qq++) {
        float4 a = Wi4[jA * 32 + 4 * qq + kq];
        float4 c = Wi4[jB * 32 + 4 * qq + kq];
        wA[2 * qq]     = f2_to_bf2(a.x, a.y);
        wA[2 * qq + 1] = f2_to_bf2(a.z, a.w);
        wB[2 * qq]     = f2_to_bf2(c.x, c.y);
        wB[2 * qq + 1] = f2_to_bf2(c.z, c.w);
    }

    const float biasA = b_ih[jA] + b_hh[jA];
    const float biasB = b_ih[jB] + b_hh[jB];
    const size_t base_row = (size_t)blockIdx.x * 512;

    // preload tile 0: 16 rows x 32 f4 = 512 f4, one per thread
    ((float4*)xs[0])[tid] = ((const float4*)(x + base_row * II))[tid];
    __syncthreads();

    for (int tile = 0; tile < 32; tile++) {
        const int cur = tile & 1;
        if (tile < 31) {
            ((float4*)xs[cur ^ 1])[tid] =
                ((const float4*)(x + (base_row + (size_t)(tile + 1) * 16) * II))[tid];
        }

        const size_t r0 = base_row + (size_t)tile * 16;
#pragma unroll
        for (int r = 0; r < 16; r++) {
            const float4* xr = (const float4*)(xs[cur] + r * II);
            float2 aA0 = make_float2(0.0f, 0.0f), aA1 = aA0;
            float2 aB0 = aA0, aB1 = aA0;
#pragma unroll
            for (int qq = 0; qq < 8; qq++) {
                float4 xv = xr[4 * qq + kq];      // 64B warp run: 1 wavefront
                float2 x01 = make_float2(xv.x, xv.y);
                float2 x23 = make_float2(xv.z, xv.w);
                aA0 = ffma2(x01, bf2_lo_higarbage(wA[2 * qq]),     aA0);
                aA1 = ffma2(x23, bf2_lo_higarbage(wA[2 * qq + 1]), aA1);
                aB0 = ffma2(x01, bf2_lo_higarbage(wB[2 * qq]),     aB0);
                aB1 = ffma2(x23, bf2_lo_higarbage(wB[2 * qq + 1]), aB1);
            }
            float dA = (aA0.x + aA0.y) + (aA1.x + aA1.y);
            float dB = (aB0.x + aB0.y) + (aB1.x + aB1.y);
            dA += __shfl_xor_sync(0xffffffffu, dA, 1);
            dB += __shfl_xor_sync(0xffffffffu, dB, 1);
            dA += __shfl_xor_sync(0xffffffffu, dA, 2);
            dB += __shfl_xor_sync(0xffffffffu, dB, 2);
            if (kq == 0) {
                g_xp[(r0 + r) * HH + jA] = dA + biasA;
                g_xp[(r0 + r) * HH + jB] = dB + biasB;
            }
        }
        __syncthreads();
    }
}

// ---------------------------------------------------------------------------
// Phase 2 + 3: recurrent scan — EXACT R12 (validated best: 420 us, no spill).
// PARITY-PAIR: warp w, lane l -> j = w*16 + (l>>1), p = l&1. W f4 idx
// {2qq+p}: qq<22 fp32 regs (88 regs), qq=22..31 bf16 pairs in SMEM (5 uint4
// loads/step). h fp32 broadcast (1 wf/load). shfl.xor(1); ONE bar/step.
// ---------------------------------------------------------------------------
#define NREG 22

__global__ void __launch_bounds__(512, 1)
rnn_scan(const float* __restrict__ W_hh,
         const float* __restrict__ W_fc,
         const float* __restrict__ b_fc,
         float* __restrict__ out) {
    extern __shared__ float sm[];
    uint4* wtU = (uint4*)sm;                    // [5][512] uint4 = 40 KB
    float* hA  = sm + 5 * 512 * 4;              // 256 floats
    float* hB  = hA + HH;                       // 256 floats
    float* red = hB + HH;                       // 8 floats

    const int tid  = threadIdx.x;
    const int lane = tid & 31;
    const int w    = tid >> 5;
    const int j    = (w << 4) | (lane >> 1);    // 0..255
    const int p    = lane & 1;
    const int b    = blockIdx.x;

    const float4* W4 = (const float4*)W_hh;     // row j = W4[j*64 .. +63]

    float4 wreg[NREG];
#pragma unroll
    for (int qq = 0; qq < NREG; qq++) wreg[qq] = W4[j * 64 + 2 * qq + p];

#pragma unroll
    for (int s = 0; s < 5; s++) {
        float4 wa = W4[j * 64 + 2 * (NREG + 2 * s) + p];
        float4 wb = W4[j * 64 + 2 * (NREG + 2 * s + 1) + p];
        uint4 u;
        u.x = f2_to_bf2(wa.x, wa.y);
        u.y = f2_to_bf2(wa.z, wa.w);
        u.z = f2_to_bf2(wb.x, wb.y);
        u.w = f2_to_bf2(wb.z, wb.w);
        wtU[s * 512 + j * 2 + p] = u;
    }

    if (tid < HH) { hA[tid] = 0.0f; hB[tid] = 0.0f; }
    __syncthreads();

    const float* xp  = g_xp + (size_t)b * TT * HH + j;
    const uint4* wtp = wtU + j * 2 + p;         // wtp[s*512]

    float* hcur = hA;
    float* hnxt = hB;

    float xpv = xp[0];                          // pipeline head

    for (int t = 0; t < TT; t++) {
        const float4* hs4 = (const float4*)hcur;
        float2 a0 = make_float2(0.0f, 0.0f), a1 = a0, a2 = a0, a3 = a0;

        // bf16 W-tail first: LDS latency overlaps the register-W FMA stream
#pragma unroll
        for (int s = 0; s < 5; s++) {
            uint4 wv = wtp[s * 512];
            float4 ha = hs4[2 * (NREG + 2 * s) + p];
            float4 hb = hs4[2 * (NREG + 2 * s + 1) + p];
            a0 = ffma2(make_float2(ha.x, ha.y), bf2_lo_higarbage(wv.x), a0);
            a1 = ffma2(make_float2(ha.z, ha.w), bf2_lo_higarbage(wv.y), a1);
            a2 = ffma2(make_float2(hb.x, hb.y), bf2_lo_higarbage(wv.z), a2);
            a3 = ffma2(make_float2(hb.z, hb.w), bf2_lo_higarbage(wv.w), a3);
        }
#pragma unroll
        for (int qq = 0; qq < NREG; qq++) {
            float4 h4 = hs4[2 * qq + p];
            if (qq & 1) {
                a2 = ffma2(make_float2(h4.x, h4.y), make_float2(wreg[qq].x, wreg[qq].y), a2);
                a3 = ffma2(make_float2(h4.z, h4.w), make_float2(wreg[qq].z, wreg[qq].w), a3);
            } else {
                a0 = ffma2(make_float2(h4.x, h4.y), make_float2(wreg[qq].x, wreg[qq].y), a0);
                a1 = ffma2(make_float2(h4.z, h4.w), make_float2(wreg[qq].z, wreg[qq].w), a1);
            }
        }

        // prefetch next step's xp while the exchange/tanh drains
        float xpn = 0.0f;
        if (t + 1 < TT) xpn = xp[(size_t)(t + 1) * HH];

        const float mydot = ((a0.x + a0.y) + (a1.x + a1.y)) +
                            ((a2.x + a2.y) + (a3.x + a3.y));

        const float other = __shfl_xor_sync(0xffffffffu, mydot, 1);
        const float hn = fast_tanh(xpv + mydot + other);  // identical in pair

        if (p == 0) hnxt[j] = hn;               // even lanes publish
        __syncthreads();                        // single barrier per step

        xpv = xpn;
        float* tmp = hcur; hcur = hnxt; hnxt = tmp;
    }

    // Phase 3: out[b] = sigmoid(h . W_fc + b_fc)
    if (tid < HH) {
        float v = hcur[tid] * W_fc[tid];
#pragma unroll
        for (int o = 16; o > 0; o >>= 1) v += __shfl_down_sync(0xffffffffu, v, o);
        if ((tid & 31) == 0) red[tid >> 5] = v;
    }
    __syncthreads();
    if (tid == 0) {
        float s = b_fc[0];
#pragma unroll
        for (int w2 = 0; w2 < 8; w2++) s += red[w2];
        out[b] = 1.0f / (1.0f + expf(-s));
    }
}

// ---------------------------------------------------------------------------

extern "C" void kernel_launch(void* const* d_in, const int* in_sizes, int n_in,
                              void* d_out, int out_size) {
    const float* x    = (const float*)d_in[0];
    const float* W_ih = (const float*)d_in[1];
    const float* W_hh = (const float*)d_in[2];
    const float* b_ih = (const float*)d_in[3];
    const float* b_hh = (const float*)d_in[4];
    const float* W_fc = (const float*)d_in[5];
    const float* b_fc = (const float*)d_in[6];
    float* out = (float*)d_out;

    const int smem_b = (5 * 512 * 4 + 2 * HH + 8) * (int)sizeof(float);  // ~42 KB
    cudaFuncSetAttribute(rnn_scan, cudaFuncAttributeMaxDynamicSharedMemorySize, smem_b);

    rnn_xproj<<<128, 512>>>(x, W_ih, b_ih, b_hh);
    rnn_scan<<<BB, 512, smem_b>>>(W_hh, W_fc, b_fc, out);
}